// round 9
// baseline (speedup 1.0000x reference)
#include <cuda_runtime.h>
#include <cuda_fp16.h>
#include <cstdint>

#define NTOK 8192
#define HDIM 1024
#define FDIM 4096
#define NEXP 8

#define BM 64
#define BK 32          /* halves per k-tile */
#define NSTAGE 4
#define ROW 80         /* bytes per 32-half SMEM row (64B + 16B pad) */

#define OFF_TOK  0
#define OFF_WGT  256
#define OFF_BIAS 1024
#define OFF_A    2048
#define A_ST (BM * ROW)                /* 5120 */

// ---------------- scratch (device globals: no allocation allowed) ----------
__device__ int    g_cnt[NEXP];
__device__ int    g_off[NEXP];
__device__ int    g_tok[NEXP * NTOK];
__device__ float  g_wgt[NEXP * NTOK];
__device__ __half g_hbuf[(size_t)(2 * NTOK) * FDIM];            // 128 MB fp16
__device__ __half g_xh  [(size_t)NTOK * HDIM];                  // 16 MB  fp16 x
__device__ __half g_w1h [(size_t)NEXP * (size_t)HDIM * FDIM];   // W1^T fp16 [e][f][h]
__device__ __half g_w2h [(size_t)NEXP * (size_t)FDIM * HDIM];   // W2^T fp16 [e][h][f]

// ---------------- helpers ---------------------------------------------------
__device__ __forceinline__ uint32_t smem_u32(const void* p) {
    uint32_t a;
    asm("{ .reg .u64 t; cvta.to.shared.u64 t, %1; cvt.u32.u64 %0, t; }" : "=r"(a) : "l"(p));
    return a;
}

__device__ __forceinline__ void mma_f16(float* c, const uint32_t* a, const uint32_t* b) {
    asm("mma.sync.aligned.m16n8k16.row.col.f32.f16.f16.f32 "
        "{%0,%1,%2,%3}, {%4,%5,%6,%7}, {%8,%9}, {%0,%1,%2,%3};"
        : "+f"(c[0]), "+f"(c[1]), "+f"(c[2]), "+f"(c[3])
        : "r"(a[0]), "r"(a[1]), "r"(a[2]), "r"(a[3]),
          "r"(b[0]), "r"(b[1]));
}

#define LDSM4(r0, r1, r2, r3, addr) \
    asm volatile("ldmatrix.sync.aligned.m8n8.x4.shared.b16 {%0,%1,%2,%3}, [%4];" \
                 : "=r"(r0), "=r"(r1), "=r"(r2), "=r"(r3) : "r"(addr))

__device__ __forceinline__ float gelu_exact(float v) {
    return 0.5f * v * (1.0f + erff(v * 0.70710678118654752440f));
}

#define CP16(dst, src) \
    asm volatile("cp.async.cg.shared.global [%0], [%1], 16;" \
                 :: "r"((uint32_t)(dst)), "l"(__cvta_generic_to_global(src)))
#define CP_COMMIT() asm volatile("cp.async.commit_group;" ::: "memory")

// ---------------- coarse transpose helper (32 rows x 512 cols per call) -----
// src[e][R][C] fp32 -> dst[e][C][R] fp16, staging buffer 32x33 floats.
__device__ __forceinline__ void transpose_coarse(const float* __restrict__ src,
                                                 __half* __restrict__ dst,
                                                 int R, int C, int id,
                                                 float (*tb)[33]) {
    const int tilesR = R / 32;
    const int perExp = tilesR * (C / 512);
    const int e  = id / perExp;
    const int rm = id % perExp;
    const int r0 = (rm % tilesR) * 32;
    const int c0 = (rm / tilesR) * 512;
    const float* s = src + (size_t)e * R * C;
    __half* d = dst + (size_t)e * R * C;
    const int tx = threadIdx.x & 31, ty = threadIdx.x >> 5;
    for (int cs = 0; cs < 512; cs += 32) {
        #pragma unroll
        for (int i = 0; i < 4; i++)
            tb[ty + i * 8][tx] = s[(size_t)(r0 + ty + i * 8) * C + c0 + cs + tx];
        __syncthreads();
        #pragma unroll
        for (int i = 0; i < 4; i++)
            d[(size_t)(c0 + cs + ty + i * 8) * R + r0 + tx] =
                __float2half_rn(tb[tx][ty + i * 8]);
        __syncthreads();
    }
}

// ---------------- prep kernel: router + W1^T + x->fp16 ----------------------
#define PREP_RTR 1024
#define PREP_T1  (PREP_RTR + 2048)
#define PREP_XC  (PREP_T1 + 1024)

__global__ void prep_kernel(const float* __restrict__ x,
                            const float* __restrict__ grad,
                            const float* __restrict__ Wr,
                            const float* __restrict__ br,
                            const float* __restrict__ W1) {
    __shared__ float tb[32][33];
    const int bid = blockIdx.x;

    if (bid < PREP_RTR) {
        // ---- router: one warp per token ----
        int n = bid * 8 + (threadIdx.x >> 5);
        int lane = threadIdx.x & 31;
        float acc[NEXP];
        #pragma unroll
        for (int e = 0; e < NEXP; e++) acc[e] = 0.f;
        const float* xr = x + (size_t)n * HDIM;
        for (int h = lane; h < HDIM; h += 32) {
            float xv = xr[h];
            const float* wrow = Wr + h * NEXP;
            #pragma unroll
            for (int e = 0; e < NEXP; e++) acc[e] = fmaf(xv, wrow[e], acc[e]);
        }
        #pragma unroll
        for (int e = 0; e < NEXP; e++) {
            #pragma unroll
            for (int off = 16; off > 0; off >>= 1)
                acc[e] += __shfl_xor_sync(0xffffffffu, acc[e], off);
        }
        if (lane == 0) {
            float gv = grad[n];
            float l[NEXP];
            #pragma unroll
            for (int e = 0; e < NEXP; e++)
                l[e] = acc[e] + gv * Wr[HDIM * NEXP + e] + br[e];
            float m = l[0];
            #pragma unroll
            for (int e = 1; e < NEXP; e++) m = fmaxf(m, l[e]);
            float p[NEXP];
            float s = 0.f;
            #pragma unroll
            for (int e = 0; e < NEXP; e++) { p[e] = expf(l[e] - m); s += p[e]; }
            float inv = 1.f / s;
            int i1 = 0;
            #pragma unroll
            for (int e = 1; e < NEXP; e++) if (p[e] > p[i1]) i1 = e;
            int i2 = (i1 == 0) ? 1 : 0;
            #pragma unroll
            for (int e = 0; e < NEXP; e++) if (e != i1 && p[e] > p[i2]) i2 = e;
            int s1 = atomicAdd(&g_cnt[i1], 1);
            g_tok[i1 * NTOK + s1] = n;  g_wgt[i1 * NTOK + s1] = p[i1] * inv;
            int s2 = atomicAdd(&g_cnt[i2], 1);
            g_tok[i2 * NTOK + s2] = n;  g_wgt[i2 * NTOK + s2] = p[i2] * inv;
        }
    } else if (bid < PREP_T1) {
        transpose_coarse(W1, g_w1h, HDIM, FDIM, bid - PREP_RTR, tb);
    } else if (bid < PREP_XC) {
        // x -> fp16: 32 halves per thread, coalesced
        const float4* x4 = (const float4*)x;
        const int b = bid - PREP_T1;
        #pragma unroll
        for (int j = 0; j < 4; j++) {
            size_t i = (size_t)b * 2048 + j * 512 + threadIdx.x * 2;
            float4 a0 = x4[i];
            float4 a1 = x4[i + 1];
            __half2 h[4];
            h[0] = __floats2half2_rn(a0.x, a0.y);
            h[1] = __floats2half2_rn(a0.z, a0.w);
            h[2] = __floats2half2_rn(a1.x, a1.y);
            h[3] = __floats2half2_rn(a1.z, a1.w);
            *(uint4*)(g_xh + i * 4) = *(uint4*)h;
        }
    }
}

__global__ void prefix_kernel() {
    if (threadIdx.x == 0) {
        int s = 0;
        #pragma unroll
        for (int e = 0; e < NEXP; e++) { g_off[e] = s; s += g_cnt[e]; }
    }
}

// ---------------- pipelined grouped GEMM (fp16 HMMA, BM x BN_ tile) ----------
// A[BM,KDIM] k-major fp16 (gathered rows). B^T[n][k] k-contiguous fp16.
// IS_G1: A = g_xh by token, B = g_w1h  -> gelu -> g_hbuf (fp16)
//        extra blocks (blockIdx.x >= GX) perform the W2 transpose (overlapped).
// else : A = g_hbuf rows,   B = g_w2h  -> w*(.+b2) atomic -> out (fp32)
template<int KDIM, int BN_, bool IS_G1>
__global__ __launch_bounds__(256, 2) void moe_gemm(const float* __restrict__ bias,
                                                   float* __restrict__ out,
                                                   const float* __restrict__ W2) {
    constexpr int B_ST = BN_ * ROW;
    constexpr int OFF_B = OFF_A + NSTAGE * A_ST;
    constexpr int WN = BN_ / 4;        /* n-cols per warp */
    constexpr int NT = BN_ / 32;       /* n8-frags per warp */
    constexpr int NBC = BN_ / 64;      /* B cp.async chunks per thread */
    constexpr int GX = (IS_G1 ? FDIM : HDIM) / BN_;

    extern __shared__ char smem[];

    if (IS_G1 && blockIdx.x >= GX) {
        // -------- fused W2 transpose (runs under gemm1's idle DRAM) --------
        const int id = (blockIdx.x - GX) + GX * (blockIdx.y + 128 * blockIdx.z);
        if (id < 2048)
            transpose_coarse(W2, g_w2h, FDIM, HDIM, id, (float(*)[33])smem);
        return;
    }

    const int e = blockIdx.z;
    const int cnt = g_cnt[e];
    const int row0 = blockIdx.y * BM;
    if (row0 >= cnt) return;
    const int off = g_off[e];
    const int n0 = blockIdx.x * BN_;

    const uint32_t sb = smem_u32(smem);
    const int tid  = threadIdx.x;
    const int lane = tid & 31;
    const int warp = tid >> 5;
    const int wm = warp >> 2;       // 0..1 (32 rows each)
    const int wn = warp & 3;        // 0..3 (WN cols each)
    const int g  = lane >> 2;       // 0..7
    const int tig = lane & 3;       // 0..3

    int*   tok_s  = (int*)(smem + OFF_TOK);
    float* wgt_s  = (float*)(smem + OFF_WGT);
    float* bias_s = (float*)(smem + OFF_BIAS);

    if (tid < BM) {
        int gr = row0 + tid;
        int sr = (gr < cnt) ? gr : (cnt - 1);
        tok_s[tid] = g_tok[e * NTOK + sr];
        wgt_s[tid] = g_wgt[e * NTOK + sr];
    }
    if (tid < BN_)
        bias_s[tid] = bias[(size_t)e * (IS_G1 ? FDIM : HDIM) + n0 + tid];
    __syncthreads();

    // ---- cp.async geometry (16B = 8 halves per chunk) ----
    const __half* aptr;
    {
        int r = tid >> 2;
        if (IS_G1) {
            aptr = g_xh + (size_t)tok_s[r] * HDIM + (tid & 3) * 8;
        } else {
            int gr = row0 + r;
            int sr = (gr < cnt) ? gr : (cnt - 1);
            aptr = g_hbuf + (size_t)(off + sr) * FDIM + (tid & 3) * 8;
        }
    }
    const __half* wsrc = IS_G1 ? g_w1h : g_w2h;
    const __half* bptr = wsrc + (size_t)e * HDIM * FDIM
                       + (size_t)(n0 + (tid >> 2)) * KDIM + (tid & 3) * 8;
    const uint32_t dA0 = sb + OFF_A + (tid >> 2) * ROW + (tid & 3) * 16;
    const uint32_t dB0 = sb + OFF_B + (tid >> 2) * ROW + (tid & 3) * 16;

    // ---- LDSM per-lane base addresses ----
    const uint32_t a_off = sb + OFF_A + (uint32_t)(wm * 32 + (lane & 15)) * ROW
                         + ((lane >> 4) & 1) * 16;
    const uint32_t b_off = sb + OFF_B
                         + (uint32_t)(wn * WN + (lane & 7) + ((lane >> 4) & 1) * 8) * ROW
                         + ((lane >> 3) & 1) * 16;

    constexpr int NK = KDIM / BK;

    #define LOAD_TILE(T) do { \
        const int _s = (T) % NSTAGE; \
        CP16(dA0 + _s * A_ST, aptr + (T) * BK); \
        const uint32_t _db = dB0 + _s * B_ST; \
        _Pragma("unroll") \
        for (int _i = 0; _i < NBC; _i++) \
            CP16(_db + _i * (64 * ROW), bptr + (size_t)_i * 64 * KDIM + (T) * BK); \
        CP_COMMIT(); \
    } while (0)

    float acc[2][NT][4];
    #pragma unroll
    for (int mt = 0; mt < 2; mt++)
        #pragma unroll
        for (int nt = 0; nt < NT; nt++)
            #pragma unroll
            for (int i = 0; i < 4; i++) acc[mt][nt][i] = 0.f;

    LOAD_TILE(0);
    LOAD_TILE(1);
    LOAD_TILE(2);

    for (int kt = 0; kt < NK; ++kt) {
        if (kt + 3 <= NK) {
            asm volatile("cp.async.wait_group 2;" ::: "memory");
        } else if (kt + 2 == NK) {
            asm volatile("cp.async.wait_group 1;" ::: "memory");
        } else {
            asm volatile("cp.async.wait_group 0;" ::: "memory");
        }
        __syncthreads();
        if (kt + 3 < NK) LOAD_TILE(kt + 3);

        const int s = kt % NSTAGE;
        const uint32_t sA = a_off + s * A_ST;
        const uint32_t sB = b_off + s * B_ST;

        #pragma unroll
        for (int ks = 0; ks < 2; ks++) {           // two k16 steps per 32-half tile
            uint32_t a[2][4], b[NT][2];
            #pragma unroll
            for (int mt = 0; mt < 2; mt++)
                LDSM4(a[mt][0], a[mt][1], a[mt][2], a[mt][3],
                      sA + mt * (16 * ROW) + ks * 32);
            #pragma unroll
            for (int j = 0; j < NT / 2; j++)
                LDSM4(b[2 * j][0], b[2 * j][1], b[2 * j + 1][0], b[2 * j + 1][1],
                      sB + j * (16 * ROW) + ks * 32);
            #pragma unroll
            for (int mt = 0; mt < 2; mt++)
                #pragma unroll
                for (int nt = 0; nt < NT; nt++)
                    mma_f16(acc[mt][nt], a[mt], b[nt]);
        }
    }
    #undef LOAD_TILE
    __syncthreads();

    // ---- epilogue ----
    #pragma unroll
    for (int mt = 0; mt < 2; mt++) {
        #pragma unroll
        for (int half = 0; half < 2; half++) {
            const int rl = wm * 32 + mt * 16 + g + half * 8;
            const int gr = row0 + rl;
            if (gr < cnt) {
                if (IS_G1) {
                    __half* hrow = g_hbuf + (size_t)(off + gr) * FDIM + n0 + wn * WN;
                    #pragma unroll
                    for (int nt = 0; nt < NT; nt++) {
                        int c = nt * 8 + tig * 2;
                        float v0 = gelu_exact(acc[mt][nt][half * 2 + 0] + bias_s[wn * WN + c]);
                        float v1 = gelu_exact(acc[mt][nt][half * 2 + 1] + bias_s[wn * WN + c + 1]);
                        *(__half2*)(hrow + c) = __floats2half2_rn(v0, v1);
                    }
                } else {
                    const int   tok = tok_s[rl];
                    const float w   = wgt_s[rl];
                    float* orow = out + (size_t)tok * HDIM + n0 + wn * WN;
                    #pragma unroll
                    for (int nt = 0; nt < NT; nt++) {
                        int c = nt * 8 + tig * 2;
                        float v0 = w * (acc[mt][nt][half * 2 + 0] + bias_s[wn * WN + c]);
                        float v1 = w * (acc[mt][nt][half * 2 + 1] + bias_s[wn * WN + c + 1]);
                        atomicAdd(orow + c,     v0);
                        atomicAdd(orow + c + 1, v1);
                    }
                }
            }
        }
    }
}

// ---------------- launch -----------------------------------------------------
extern "C" void kernel_launch(void* const* d_in, const int* in_sizes, int n_in,
                              void* d_out, int out_size) {
    const float* x    = (const float*)d_in[0];
    const float* grad = (const float*)d_in[1];
    const float* Wr   = (const float*)d_in[2];
    const float* br   = (const float*)d_in[3];
    const float* W1   = (const float*)d_in[4];
    const float* b1   = (const float*)d_in[5];
    const float* W2   = (const float*)d_in[6];
    const float* b2   = (const float*)d_in[7];
    float* out = (float*)d_out;

    constexpr int SMEM_G1 = OFF_A + NSTAGE * A_ST + NSTAGE * (256 * ROW);  /* 104448 */
    constexpr int SMEM_G2 = OFF_A + NSTAGE * A_ST + NSTAGE * (128 * ROW);  /* 63488 */

    cudaFuncSetAttribute(moe_gemm<HDIM, 256, true>,
                         cudaFuncAttributeMaxDynamicSharedMemorySize, SMEM_G1);
    cudaFuncSetAttribute(moe_gemm<FDIM, 128, false>,
                         cudaFuncAttributeMaxDynamicSharedMemorySize, SMEM_G2);

    // zero output + counters via memset nodes (graph-legal)
    void* cntp; cudaGetSymbolAddress(&cntp, g_cnt);
    cudaMemsetAsync(cntp, 0, NEXP * sizeof(int));
    cudaMemsetAsync(out, 0, (size_t)out_size * sizeof(float));

    prep_kernel<<<PREP_XC, 256>>>(x, grad, Wr, br, W1);
    prefix_kernel<<<1, 32>>>();

    // gemm1: x-dim doubled; blocks with x >= 16 perform the W2 transpose
    moe_gemm<HDIM, 256, true>
        <<<dim3(2 * (FDIM / 256), NTOK / BM, NEXP), 256, SMEM_G1>>>(b1, nullptr, W2);
    moe_gemm<FDIM, 128, false>
        <<<dim3(HDIM / 128, NTOK / BM, NEXP), 256, SMEM_G2>>>(b2, out, nullptr);
}

// round 10
// speedup vs baseline: 1.1106x; 1.1106x over previous
#include <cuda_runtime.h>
#include <cuda_fp16.h>
#include <cstdint>

#define NTOK 8192
#define HDIM 1024
#define FDIM 4096
#define NEXP 8

#define BM 64
#define BK 32          /* halves per k-tile */
#define NSTAGE 4
#define ROW 80         /* A: bytes per 32-half row (64B + 16B pad) */

#define OFF_TOK  0
#define OFF_WGT  256
#define OFF_BIAS 1024
#define OFF_A    2048
#define A_ST (BM * ROW)                /* 5120 */
#define OFF_B (OFF_A + NSTAGE * A_ST)  /* 22528 */

// ---------------- scratch (device globals: no allocation allowed) ----------
__device__ int    g_cnt[NEXP];
__device__ int    g_off[NEXP];
__device__ int    g_tok[NEXP * NTOK];
__device__ float  g_wgt[NEXP * NTOK];
__device__ __half g_hbuf[(size_t)(2 * NTOK) * FDIM];            // 128 MB fp16
__device__ __half g_xh  [(size_t)NTOK * HDIM];                  // fp16 x
__device__ __half g_w1h [(size_t)NEXP * (size_t)HDIM * FDIM];   // fp16 W1 [e][h][f]
__device__ __half g_w2h [(size_t)NEXP * (size_t)FDIM * HDIM];   // fp16 W2 [e][f][h]

// ---------------- helpers ---------------------------------------------------
__device__ __forceinline__ uint32_t smem_u32(const void* p) {
    uint32_t a;
    asm("{ .reg .u64 t; cvta.to.shared.u64 t, %1; cvt.u32.u64 %0, t; }" : "=r"(a) : "l"(p));
    return a;
}

__device__ __forceinline__ void mma_f16(float* c, const uint32_t* a, const uint32_t* b) {
    asm("mma.sync.aligned.m16n8k16.row.col.f32.f16.f16.f32 "
        "{%0,%1,%2,%3}, {%4,%5,%6,%7}, {%8,%9}, {%0,%1,%2,%3};"
        : "+f"(c[0]), "+f"(c[1]), "+f"(c[2]), "+f"(c[3])
        : "r"(a[0]), "r"(a[1]), "r"(a[2]), "r"(a[3]),
          "r"(b[0]), "r"(b[1]));
}

#define LDSM4(r0, r1, r2, r3, addr) \
    asm volatile("ldmatrix.sync.aligned.m8n8.x4.shared.b16 {%0,%1,%2,%3}, [%4];" \
                 : "=r"(r0), "=r"(r1), "=r"(r2), "=r"(r3) : "r"(addr))

#define LDSM4T(r0, r1, r2, r3, addr) \
    asm volatile("ldmatrix.sync.aligned.m8n8.x4.trans.shared.b16 {%0,%1,%2,%3}, [%4];" \
                 : "=r"(r0), "=r"(r1), "=r"(r2), "=r"(r3) : "r"(addr))

__device__ __forceinline__ float gelu_exact(float v) {
    return 0.5f * v * (1.0f + erff(v * 0.70710678118654752440f));
}

#define CP16(dst, src) \
    asm volatile("cp.async.cg.shared.global [%0], [%1], 16;" \
                 :: "r"((uint32_t)(dst)), "l"(__cvta_generic_to_global(src)))
#define CP_COMMIT() asm volatile("cp.async.commit_group;" ::: "memory")

// convert 8 fp32 -> 8 fp16 (two float4 loads, one uint4 store)
__device__ __forceinline__ void cvt8(const float4* __restrict__ src4, size_t hidx,
                                     __half* __restrict__ dst) {
    float4 a0 = src4[hidx / 4];
    float4 a1 = src4[hidx / 4 + 1];
    __half2 h[4];
    h[0] = __floats2half2_rn(a0.x, a0.y);
    h[1] = __floats2half2_rn(a0.z, a0.w);
    h[2] = __floats2half2_rn(a1.x, a1.y);
    h[3] = __floats2half2_rn(a1.z, a1.w);
    *(uint4*)(dst + hidx) = *(uint4*)h;
}

// ---------------- prep kernel: router | W1 cvt | x cvt ----------------------
#define PREP_RTR 1024
#define PREP_W1  (PREP_RTR + 2048)
#define PREP_XC  (PREP_W1 + 1024)

__global__ void prep_kernel(const float* __restrict__ x,
                            const float* __restrict__ grad,
                            const float* __restrict__ Wr,
                            const float* __restrict__ br,
                            const float* __restrict__ W1) {
    const int bid = blockIdx.x;
    const int tid = threadIdx.x;

    if (bid < PREP_RTR) {
        // ---- router: one warp per token ----
        int n = bid * 8 + (tid >> 5);
        int lane = tid & 31;
        float acc[NEXP];
        #pragma unroll
        for (int e = 0; e < NEXP; e++) acc[e] = 0.f;
        const float* xr = x + (size_t)n * HDIM;
        for (int h = lane; h < HDIM; h += 32) {
            float xv = xr[h];
            const float* wrow = Wr + h * NEXP;
            #pragma unroll
            for (int e = 0; e < NEXP; e++) acc[e] = fmaf(xv, wrow[e], acc[e]);
        }
        #pragma unroll
        for (int e = 0; e < NEXP; e++) {
            #pragma unroll
            for (int off = 16; off > 0; off >>= 1)
                acc[e] += __shfl_xor_sync(0xffffffffu, acc[e], off);
        }
        if (lane == 0) {
            float gv = grad[n];
            float l[NEXP];
            #pragma unroll
            for (int e = 0; e < NEXP; e++)
                l[e] = acc[e] + gv * Wr[HDIM * NEXP + e] + br[e];
            float m = l[0];
            #pragma unroll
            for (int e = 1; e < NEXP; e++) m = fmaxf(m, l[e]);
            float p[NEXP];
            float s = 0.f;
            #pragma unroll
            for (int e = 0; e < NEXP; e++) { p[e] = expf(l[e] - m); s += p[e]; }
            float inv = 1.f / s;
            int i1 = 0;
            #pragma unroll
            for (int e = 1; e < NEXP; e++) if (p[e] > p[i1]) i1 = e;
            int i2 = (i1 == 0) ? 1 : 0;
            #pragma unroll
            for (int e = 0; e < NEXP; e++) if (e != i1 && p[e] > p[i2]) i2 = e;
            int s1 = atomicAdd(&g_cnt[i1], 1);
            g_tok[i1 * NTOK + s1] = n;  g_wgt[i1 * NTOK + s1] = p[i1] * inv;
            int s2 = atomicAdd(&g_cnt[i2], 1);
            g_tok[i2 * NTOK + s2] = n;  g_wgt[i2 * NTOK + s2] = p[i2] * inv;
        }
    } else if (bid < PREP_W1) {
        // ---- W1 fp32 -> fp16 (same layout), 16384 halves per block ----
        const int b = bid - PREP_RTR;
        #pragma unroll
        for (int j = 0; j < 8; j++)
            cvt8((const float4*)W1, (size_t)b * 16384 + j * 2048 + tid * 8, g_w1h);
    } else {
        // ---- x fp32 -> fp16, 8192 halves per block ----
        const int b = bid - PREP_W1;
        #pragma unroll
        for (int j = 0; j < 4; j++)
            cvt8((const float4*)x, (size_t)b * 8192 + j * 2048 + tid * 8, g_xh);
    }
}

__global__ void prefix_kernel() {
    if (threadIdx.x == 0) {
        int s = 0;
        #pragma unroll
        for (int e = 0; e < NEXP; e++) { g_off[e] = s; s += g_cnt[e]; }
    }
}

// ---------------- pipelined grouped GEMM (fp16 HMMA, LDSM.T for B) ----------
// A[BM,KDIM] k-major fp16 (gathered rows). B natural layout [k][n] fp16.
// IS_G1: A = g_xh by token, B = g_w1h -> gelu -> g_hbuf; warp 8 converts W2.
// else : A = g_hbuf rows,   B = g_w2h -> w*(.+b2) atomic -> out (fp32)
template<int KDIM, int NSTRIDE, int BN_, int NTHREADS, bool IS_G1>
__global__ __launch_bounds__(NTHREADS, 2) void moe_gemm(const float* __restrict__ bias,
                                                        float* __restrict__ out,
                                                        const float* __restrict__ W2src) {
    constexpr int BROW = BN_ * 2 + 16;  /* B smem row bytes: n-contig + 16B pad */
    constexpr int B_ST = BK * BROW;
    constexpr int WN = BN_ / 4;         /* n-cols per warp */
    constexpr int NT = BN_ / 32;        /* n8-frags per warp */

    const int tid  = threadIdx.x;
    const int warp = tid >> 5;

    if (IS_G1 && warp == 8) {
        // ---- W2 convert warp: 2048 halves per block, rides idle DRAM ----
        const int id = blockIdx.x + gridDim.x * (blockIdx.y + gridDim.y * blockIdx.z);
        const int lane = tid & 31;
        #pragma unroll
        for (int j = 0; j < 8; j++)
            cvt8((const float4*)W2src, (size_t)id * 2048 + j * 256 + lane * 8, g_w2h);
        return;
    }

    #define BAR() do { \
        if (IS_G1) asm volatile("bar.sync 1, 256;" ::: "memory"); \
        else __syncthreads(); \
    } while (0)

    const int e = blockIdx.z;
    const int cnt = g_cnt[e];
    const int row0 = blockIdx.y * BM;
    if (row0 >= cnt) return;
    const int off = g_off[e];
    const int n0 = blockIdx.x * BN_;

    extern __shared__ char smem[];
    const uint32_t sb = smem_u32(smem);
    const int lane = tid & 31;
    const int wm = warp >> 2;       // 0..1 (32 rows each)
    const int wn = warp & 3;        // 0..3 (WN cols each)
    const int g  = lane >> 2;       // 0..7
    const int tig = lane & 3;       // 0..3

    int*   tok_s  = (int*)(smem + OFF_TOK);
    float* wgt_s  = (float*)(smem + OFF_WGT);
    float* bias_s = (float*)(smem + OFF_BIAS);

    if (tid < BM) {
        int gr = row0 + tid;
        int sr = (gr < cnt) ? gr : (cnt - 1);
        tok_s[tid] = g_tok[e * NTOK + sr];
        wgt_s[tid] = g_wgt[e * NTOK + sr];
    }
    if (tid < BN_)
        bias_s[tid] = bias[(size_t)e * NSTRIDE + n0 + tid];
    BAR();

    // ---- cp.async geometry ----
    // A: 1 chunk/thread: row tid>>2 (0..63), 16B chunk tid&3
    const __half* aptr;
    {
        int r = tid >> 2;
        if (IS_G1) {
            aptr = g_xh + (size_t)tok_s[r] * HDIM + (tid & 3) * 8;
        } else {
            int gr = row0 + r;
            int sr = (gr < cnt) ? gr : (cnt - 1);
            aptr = g_hbuf + (size_t)(off + sr) * FDIM + (tid & 3) * 8;
        }
    }
    const uint32_t dA0 = sb + OFF_A + (tid >> 2) * ROW + (tid & 3) * 16;

    // B: natural [k][n]. BN256: row tid>>5 (+8i), chunk tid&31 (i<4).
    //                    BN128: row tid>>4 (+16i), chunk tid&15 (i<2).
    constexpr int BLG = (BN_ == 256) ? 5 : 4;   /* log2 chunks per row */
    constexpr int BRI = 256 >> BLG;             /* rows covered per pass */
    constexpr int NBI = BK / BRI;               /* passes */
    const int bRow = tid >> BLG;
    const int bCh  = tid & ((1 << BLG) - 1);
    const __half* wsrc = IS_G1 ? g_w1h : g_w2h;
    const __half* bptr = wsrc + (size_t)e * HDIM * FDIM
                       + (size_t)bRow * NSTRIDE + n0 + bCh * 8;
    const uint32_t dB0 = sb + OFF_B + bRow * BROW + bCh * 16;

    // ---- LDSM per-lane base addresses ----
    const uint32_t a_off = sb + OFF_A + (uint32_t)(wm * 32 + (lane & 15)) * ROW
                         + ((lane >> 4) & 1) * 16;
    // B trans: lane = k-row (lane&15), n-offset (lane>>4)*8
    const uint32_t b_off = sb + OFF_B + (uint32_t)(lane & 15) * BROW
                         + (uint32_t)(wn * WN + ((lane >> 4) & 1) * 8) * 2;

    constexpr int NK = KDIM / BK;

    #define LOAD_TILE(T) do { \
        const int _s = (T) % NSTAGE; \
        CP16(dA0 + _s * A_ST, aptr + (T) * BK); \
        const uint32_t _db = dB0 + _s * B_ST; \
        _Pragma("unroll") \
        for (int _i = 0; _i < NBI; _i++) \
            CP16(_db + _i * (BRI * BROW), \
                 bptr + ((size_t)(T) * BK + _i * BRI) * NSTRIDE); \
        CP_COMMIT(); \
    } while (0)

    float acc[2][NT][4];
    #pragma unroll
    for (int mt = 0; mt < 2; mt++)
        #pragma unroll
        for (int nt = 0; nt < NT; nt++)
            #pragma unroll
            for (int i = 0; i < 4; i++) acc[mt][nt][i] = 0.f;

    LOAD_TILE(0);
    LOAD_TILE(1);
    LOAD_TILE(2);

    for (int kt = 0; kt < NK; ++kt) {
        if (kt + 3 <= NK) {
            asm volatile("cp.async.wait_group 2;" ::: "memory");
        } else if (kt + 2 == NK) {
            asm volatile("cp.async.wait_group 1;" ::: "memory");
        } else {
            asm volatile("cp.async.wait_group 0;" ::: "memory");
        }
        BAR();
        if (kt + 3 < NK) LOAD_TILE(kt + 3);

        const int s = kt % NSTAGE;
        const uint32_t sA = a_off + s * A_ST;
        const uint32_t sB = b_off + s * B_ST;

        #pragma unroll
        for (int ks = 0; ks < 2; ks++) {           // two k16 steps per 32-half tile
            uint32_t a[2][4], b[NT][2];
            #pragma unroll
            for (int mt = 0; mt < 2; mt++)
                LDSM4(a[mt][0], a[mt][1], a[mt][2], a[mt][3],
                      sA + mt * (16 * ROW) + ks * 32);
            #pragma unroll
            for (int j = 0; j < NT / 2; j++)
                LDSM4T(b[2 * j][0], b[2 * j][1], b[2 * j + 1][0], b[2 * j + 1][1],
                       sB + ks * (16 * BROW) + j * 32);
            #pragma unroll
            for (int mt = 0; mt < 2; mt++)
                #pragma unroll
                for (int nt = 0; nt < NT; nt++)
                    mma_f16(acc[mt][nt], a[mt], b[nt]);
        }
    }
    #undef LOAD_TILE
    BAR();

    // ---- epilogue ----
    #pragma unroll
    for (int mt = 0; mt < 2; mt++) {
        #pragma unroll
        for (int half = 0; half < 2; half++) {
            const int rl = wm * 32 + mt * 16 + g + half * 8;
            const int gr = row0 + rl;
            if (gr < cnt) {
                if (IS_G1) {
                    __half* hrow = g_hbuf + (size_t)(off + gr) * FDIM + n0 + wn * WN;
                    #pragma unroll
                    for (int nt = 0; nt < NT; nt++) {
                        int c = nt * 8 + tig * 2;
                        float v0 = gelu_exact(acc[mt][nt][half * 2 + 0] + bias_s[wn * WN + c]);
                        float v1 = gelu_exact(acc[mt][nt][half * 2 + 1] + bias_s[wn * WN + c + 1]);
                        *(__half2*)(hrow + c) = __floats2half2_rn(v0, v1);
                    }
                } else {
                    const int   tok = tok_s[rl];
                    const float w   = wgt_s[rl];
                    float* orow = out + (size_t)tok * HDIM + n0 + wn * WN;
                    #pragma unroll
                    for (int nt = 0; nt < NT; nt++) {
                        int c = nt * 8 + tig * 2;
                        float v0 = w * (acc[mt][nt][half * 2 + 0] + bias_s[wn * WN + c]);
                        float v1 = w * (acc[mt][nt][half * 2 + 1] + bias_s[wn * WN + c + 1]);
                        atomicAdd(orow + c,     v0);
                        atomicAdd(orow + c + 1, v1);
                    }
                }
            }
        }
    }
    #undef BAR
}

// ---------------- launch -----------------------------------------------------
extern "C" void kernel_launch(void* const* d_in, const int* in_sizes, int n_in,
                              void* d_out, int out_size) {
    const float* x    = (const float*)d_in[0];
    const float* grad = (const float*)d_in[1];
    const float* Wr   = (const float*)d_in[2];
    const float* br   = (const float*)d_in[3];
    const float* W1   = (const float*)d_in[4];
    const float* b1   = (const float*)d_in[5];
    const float* W2   = (const float*)d_in[6];
    const float* b2   = (const float*)d_in[7];
    float* out = (float*)d_out;

    constexpr int SMEM_G1 = OFF_B + NSTAGE * (BK * (256 * 2 + 16));  /* 90112 */
    constexpr int SMEM_G2 = OFF_B + NSTAGE * (BK * (128 * 2 + 16));  /* 57344 */

    cudaFuncSetAttribute((const void*)moe_gemm<HDIM, FDIM, 256, 288, true>,
                         cudaFuncAttributeMaxDynamicSharedMemorySize, SMEM_G1);
    cudaFuncSetAttribute((const void*)moe_gemm<FDIM, HDIM, 128, 256, false>,
                         cudaFuncAttributeMaxDynamicSharedMemorySize, SMEM_G2);

    void* cntp; cudaGetSymbolAddress(&cntp, g_cnt);
    cudaMemsetAsync(cntp, 0, NEXP * sizeof(int));
    cudaMemsetAsync(out, 0, (size_t)out_size * sizeof(float));

    prep_kernel<<<PREP_XC, 256>>>(x, grad, Wr, br, W1);
    prefix_kernel<<<1, 32>>>();

    moe_gemm<HDIM, FDIM, 256, 288, true>
        <<<dim3(FDIM / 256, NTOK / BM, NEXP), 288, SMEM_G1>>>(b1, nullptr, W2);
    moe_gemm<FDIM, HDIM, 128, 256, false>
        <<<dim3(HDIM / 128, NTOK / BM, NEXP), 256, SMEM_G2>>>(b2, out, nullptr);
}